// round 2
// baseline (speedup 1.0000x reference)
#include <cuda_runtime.h>
#include <cuda_bf16.h>
#include <cub/cub.cuh>
#include <cstdint>

// ---------------- problem constants ----------------
#define FH_   50
#define FW_   84
#define A_    12
#define B_    4
#define PIX   (FH_*FW_)        // 4200
#define N_ANCH (PIX*A_)        // 50400
#define PRE   6000
#define POST  300
#define NW    94               // ceil(PRE/64)
#define NMS_THR 0.7f

static_assert(NW*64 >= PRE, "NW too small");

// correctly-rounded float exp: double exp (<=1 ulp in double) rounded to float.
// Matches glibc expf (nearly correctly rounded) with prob ~1-2^-29 per call.
__device__ __forceinline__ float exp_cr(float x) {
    return (float)exp((double)x);
}

// ---------------- static device scratch (no allocations allowed) ----------------
__device__ unsigned long long g_keys    [B_*N_ANCH];
__device__ unsigned long long g_keys_out[B_*N_ANCH];
__device__ int                g_vals    [B_*N_ANCH];
__device__ int                g_vals_out[B_*N_ANCH];
__device__ float4             g_boxes   [B_*N_ANCH];
__device__ float4             g_sboxes  [B_*PRE];
__device__ float              g_sarea   [B_*PRE];
// zero-initialized at module load; lower-triangle words are NEVER written -> stay 0
__device__ unsigned long long g_mask[(size_t)B_*PRE*NW];
__device__ unsigned char      g_temp[32u<<20];   // cub temp storage

// ---------------- kernel 1: score softmax + bbox decode ----------------
__global__ void prep_kernel(const float* __restrict__ scores,
                            const float* __restrict__ deltas,
                            const float* __restrict__ anchors,
                            const float* __restrict__ iminfo)
{
    int idx = blockIdx.x * blockDim.x + threadIdx.x;
    if (idx >= B_*N_ANCH) return;
    int pix = idx % PIX;
    int ba  = idx / PIX;
    int b   = ba / A_;
    int a   = ba % A_;

    // softmax over the (2a, 2a+1) channel pair == jax.nn.softmax semantics
    const float* sp = scores + ((size_t)(b*2*A_ + 2*a))*PIX + pix;
    float s0 = sp[0];
    float s1 = sp[PIX];
    float m  = fmaxf(s0, s1);
    float e0 = exp_cr(s0 - m);
    float e1 = exp_cr(s1 - m);
    float p  = __fdiv_rn(e1, __fadd_rn(e0, e1));

    const float* dp = deltas + ((size_t)(b*4*A_ + 4*a))*PIX + pix;
    float d0 = dp[0], d1 = dp[PIX], d2 = dp[2*PIX], d3 = dp[3*PIX];

    int i = pix*A_ + a;
    float4 an = reinterpret_cast<const float4*>(anchors)[i];

    // exact op ordering of _bbox_transform_inv; explicit *_rn blocks FMA contraction
    float w  = an.z - an.x + 1.0f;
    float h  = an.w - an.y + 1.0f;
    float cx = __fadd_rn(an.x, __fmul_rn(0.5f, w));
    float cy = __fadd_rn(an.y, __fmul_rn(0.5f, h));
    float pcx = __fadd_rn(__fmul_rn(d0, w), cx);
    float pcy = __fadd_rn(__fmul_rn(d1, h), cy);
    float pw  = __fmul_rn(exp_cr(d2), w);
    float ph  = __fmul_rn(exp_cr(d3), h);
    float hx  = __fmul_rn(0.5f, pw);
    float hy  = __fmul_rn(0.5f, ph);
    float x1  = __fsub_rn(pcx, hx);
    float y1  = __fsub_rn(pcy, hy);
    float x2  = __fadd_rn(pcx, hx);
    float y2  = __fadd_rn(pcy, hy);

    float imh = iminfo[b*4+0], imw = iminfo[b*4+1];
    float sh  = iminfo[b*4+2], sw  = iminfo[b*4+3];
    float mw  = imw - 1.0f, mh = imh - 1.0f;
    x1 = fminf(fmaxf(x1, 0.0f), mw);
    y1 = fminf(fmaxf(y1, 0.0f), mh);
    x2 = fminf(fmaxf(x2, 0.0f), mw);
    y2 = fminf(fmaxf(y2, 0.0f), mh);

    float ws = x2 - x1 + 1.0f;
    float hs = y2 - y1 + 1.0f;
    bool valid = (ws >= __fmul_rn(16.0f, sw)) && (hs >= __fmul_rn(16.0f, sh));

    // composite key: batch in bits [32,34), score in low 32 bits such that
    // ascending stable sort == per-batch descending score, ties -> lower index
    float key_f = valid ? p : -1.0f;
    unsigned int u   = __float_as_uint(key_f);
    unsigned int asc = u ^ (((unsigned int)((int)u >> 31)) | 0x80000000u);
    unsigned long long key = ((unsigned long long)(unsigned)b << 32)
                           | (unsigned long long)(unsigned)(~asc);

    int gi = b*N_ANCH + i;
    g_keys[gi]  = key;
    g_vals[gi]  = gi;
    g_boxes[gi] = make_float4(x1, y1, x2, y2);
}

// ---------------- kernel 2: gather top-PRE boxes per batch + areas ----------------
__global__ void gather_kernel()
{
    int t = blockIdx.x * blockDim.x + threadIdx.x;
    if (t >= B_*PRE) return;
    int b = t / PRE;
    int r = t % PRE;
    int v = g_vals_out[b*N_ANCH + r];
    float4 bx = g_boxes[v];
    g_sboxes[t] = bx;
    g_sarea[t]  = (bx.z - bx.x + 1.0f) * (bx.w - bx.y + 1.0f);
}

// ---------------- kernel 3: IoU suppression bitmask (upper triangle only) ----------------
__global__ void nms_mask_kernel()
{
    int cb = blockIdx.x;           // column 64-block
    int rb = blockIdx.y;           // row 64-block
    int b  = blockIdx.z;
    if (cb < rb) return;           // lower triangle: words remain zero (zero-init)

    __shared__ float4 cbox[64];
    __shared__ float  carea[64];
    int t  = threadIdx.x;
    int j0 = cb * 64;
    int jj = j0 + t;
    if (jj < PRE) { cbox[t] = g_sboxes[b*PRE + jj]; carea[t] = g_sarea[b*PRE + jj]; }
    __syncthreads();

    int i = rb * 64 + t;
    if (i >= PRE) return;
    float4 bi = g_sboxes[b*PRE + i];
    float  ai = g_sarea [b*PRE + i];

    unsigned long long bits = 0ull;
    int jmax = min(64, PRE - j0);
    #pragma unroll 4
    for (int k = 0; k < jmax; k++) {
        int j = j0 + k;
        if (j <= i) continue;
        float4 bj = cbox[k];
        float xx1 = fmaxf(bi.x, bj.x);
        float yy1 = fmaxf(bi.y, bj.y);
        float xx2 = fminf(bi.z, bj.z);
        float yy2 = fminf(bi.w, bj.w);
        float iw = fmaxf(xx2 - xx1 + 1.0f, 0.0f);
        float ih = fmaxf(yy2 - yy1 + 1.0f, 0.0f);
        float inter = __fmul_rn(iw, ih);
        float uni   = (ai + carea[k]) - inter;       // exact ref op order
        float iou   = __fdiv_rn(inter, uni);         // IEEE div, matches XLA
        if (iou > NMS_THR) bits |= (1ull << k);
    }
    g_mask[((size_t)(b*PRE + i))*NW + cb] = bits;
}

// ---------------- kernel 4: warp-serial greedy scan + output write ----------------
__global__ void nms_scan_kernel(float* __restrict__ out)
{
    int b    = blockIdx.x;
    int lane = threadIdx.x;        // 32 threads
    const unsigned FULL = 0xFFFFFFFFu;

    __shared__ unsigned long long removed[NW];
    __shared__ int keptList[POST];
    for (int w = lane; w < NW; w += 32) removed[w] = 0ull;
    __syncwarp();

    int kept = 0;
    for (int c = 0; c < NW && kept < POST; c++) {
        int r0 = c * 64;
        int ra = r0 + lane, rb2 = r0 + 32 + lane;

        // validity bits from sorted keys (valid <=> low32 key top bit clear)
        unsigned long long ka = (ra  < PRE) ? g_keys_out[b*N_ANCH + ra ] : ~0ull;
        unsigned long long kb = (rb2 < PRE) ? g_keys_out[b*N_ANCH + rb2] : ~0ull;
        unsigned lo = __ballot_sync(FULL, ((unsigned)ka & 0x80000000u) == 0u);
        unsigned hi = __ballot_sync(FULL, ((unsigned)kb & 0x80000000u) == 0u);
        unsigned long long validm = (unsigned long long)lo | ((unsigned long long)hi << 32);

        // intra-chunk suppression words, register-resident (2 rows per lane)
        unsigned long long m0 = (ra  < PRE) ? g_mask[((size_t)(b*PRE + ra ))*NW + c] : 0ull;
        unsigned long long m1 = (rb2 < PRE) ? g_mask[((size_t)(b*PRE + rb2))*NW + c] : 0ull;

        unsigned long long cand = validm & ~removed[c];
        unsigned long long keptbits = 0ull;
        while (cand && kept < POST) {                 // warp-uniform
            int l = __ffsll((long long)cand) - 1;
            keptList[kept] = r0 + l;                  // same value from all lanes
            kept++;
            keptbits |= (1ull << l);
            unsigned long long intra = (l < 32) ? __shfl_sync(FULL, m0, l)
                                                : __shfl_sync(FULL, m1, l - 32);
            cand &= ~intra;
            cand &= ~(1ull << l);
        }

        // deferred full-row ORs: loads for all newly-kept rows in flight together
        if (keptbits) {
            unsigned long long acc0 = 0, acc1 = 0, acc2 = 0;
            int w0 = lane, w1 = lane + 32, w2 = lane + 64;
            unsigned long long kb2 = keptbits;
            while (kb2) {
                int l = __ffsll((long long)kb2) - 1;
                kb2 &= kb2 - 1;
                const unsigned long long* row = &g_mask[((size_t)(b*PRE + r0 + l))*NW];
                acc0 |= row[w0];
                if (w1 < NW) acc1 |= row[w1];
                if (w2 < NW) acc2 |= row[w2];
            }
            removed[w0] |= acc0;
            if (w1 < NW) removed[w1] |= acc1;
            if (w2 < NW) removed[w2] |= acc2;
        }
        __syncwarp();
    }

    // output: (B, POST, 5) rows [b, x1, y1, x2, y2]; empty rows [b, 0,0,0,0]
    for (int r = lane; r < POST; r += 32) {
        float* o = out + ((size_t)(b*POST + r))*5;
        if (r < kept) {
            float4 bx = g_sboxes[b*PRE + keptList[r]];
            o[0] = (float)b; o[1] = bx.x; o[2] = bx.y; o[3] = bx.z; o[4] = bx.w;
        } else {
            o[0] = (float)b; o[1] = 0.0f; o[2] = 0.0f; o[3] = 0.0f; o[4] = 0.0f;
        }
    }
}

// ---------------- launch ----------------
extern "C" void kernel_launch(void* const* d_in, const int* in_sizes, int n_in,
                              void* d_out, int out_size)
{
    const float* scores  = (const float*)d_in[0];
    const float* deltas  = (const float*)d_in[1];
    const float* anchors = (const float*)d_in[2];
    const float* iminfo  = (const float*)d_in[3];
    float* out = (float*)d_out;

    void *keys, *keysOut, *vals, *valsOut, *temp;
    cudaGetSymbolAddress(&keys,    g_keys);
    cudaGetSymbolAddress(&keysOut, g_keys_out);
    cudaGetSymbolAddress(&vals,    g_vals);
    cudaGetSymbolAddress(&valsOut, g_vals_out);
    cudaGetSymbolAddress(&temp,    g_temp);

    const int total = B_ * N_ANCH;
    prep_kernel<<<(total + 255) / 256, 256>>>(scores, deltas, anchors, iminfo);

    // one stable ascending radix sort over composite (batch | ~score) keys,
    // bits [0,34) -> per-batch descending score with top_k-compatible tie order
    size_t temp_bytes = 0;
    cub::DeviceRadixSort::SortPairs(nullptr, temp_bytes,
        (const unsigned long long*)keys, (unsigned long long*)keysOut,
        (const int*)vals, (int*)valsOut, total, 0, 34);
    if (temp_bytes <= sizeof(g_temp)) {
        cub::DeviceRadixSort::SortPairs(temp, temp_bytes,
            (const unsigned long long*)keys, (unsigned long long*)keysOut,
            (const int*)vals, (int*)valsOut, total, 0, 34, (cudaStream_t)0);
    }

    gather_kernel<<<(B_*PRE + 255) / 256, 256>>>();

    dim3 mgrid(NW, NW, B_);
    nms_mask_kernel<<<mgrid, 64>>>();

    nms_scan_kernel<<<B_, 32>>>(out);
}

// round 3
// speedup vs baseline: 1.3785x; 1.3785x over previous
#include <cuda_runtime.h>
#include <cuda_bf16.h>
#include <cub/cub.cuh>
#include <cstdint>

// ---------------- problem constants ----------------
#define FH_   50
#define FW_   84
#define A_    12
#define B_    4
#define PIX   (FH_*FW_)        // 4200
#define N_ANCH (PIX*A_)        // 50400
#define PRE   6000
#define POST  300
#define NW    94               // ceil(PRE/64)
#define NMS_THR 0.7f

static_assert(NW*64 >= PRE, "NW too small");

// correctly-rounded float exp: double exp (<=1 ulp in double) rounded to float.
// Matches the reference's (CPU) expf on effectively every input.
__device__ __forceinline__ float exp_cr(float x) {
    return (float)exp((double)x);
}

// ---------------- static device scratch (no allocations allowed) ----------------
__device__ unsigned int       g_keys    [B_*N_ANCH];
__device__ unsigned int       g_keys_out[B_*N_ANCH];
__device__ int                g_vals    [B_*N_ANCH];
__device__ int                g_vals_out[B_*N_ANCH];
__device__ float4             g_boxes   [B_*N_ANCH];
__device__ float4             g_sboxes  [B_*PRE];
__device__ float              g_sarea   [B_*PRE];
// zero-initialized at module load; lower-triangle words are NEVER written -> stay 0
__device__ unsigned long long g_mask[(size_t)B_*PRE*NW];
__device__ unsigned char      g_temp[32u<<20];   // cub temp storage

// ---------------- kernel 1: score softmax + bbox decode ----------------
__global__ void prep_kernel(const float* __restrict__ scores,
                            const float* __restrict__ deltas,
                            const float* __restrict__ anchors,
                            const float* __restrict__ iminfo)
{
    int idx = blockIdx.x * blockDim.x + threadIdx.x;
    if (idx >= B_*N_ANCH) return;
    int pix = idx % PIX;
    int ba  = idx / PIX;
    int b   = ba / A_;
    int a   = ba % A_;

    // softmax over the (2a, 2a+1) channel pair == jax.nn.softmax semantics
    const float* sp = scores + ((size_t)(b*2*A_ + 2*a))*PIX + pix;
    float s0 = sp[0];
    float s1 = sp[PIX];
    float m  = fmaxf(s0, s1);
    float e0 = exp_cr(s0 - m);
    float e1 = exp_cr(s1 - m);
    float p  = __fdiv_rn(e1, __fadd_rn(e0, e1));   // p in [0, 1]

    const float* dp = deltas + ((size_t)(b*4*A_ + 4*a))*PIX + pix;
    float d0 = dp[0], d1 = dp[PIX], d2 = dp[2*PIX], d3 = dp[3*PIX];

    int i = pix*A_ + a;
    float4 an = reinterpret_cast<const float4*>(anchors)[i];

    // exact op ordering of _bbox_transform_inv; explicit *_rn blocks FMA contraction
    float w  = an.z - an.x + 1.0f;
    float h  = an.w - an.y + 1.0f;
    float cx = __fadd_rn(an.x, __fmul_rn(0.5f, w));
    float cy = __fadd_rn(an.y, __fmul_rn(0.5f, h));
    float pcx = __fadd_rn(__fmul_rn(d0, w), cx);
    float pcy = __fadd_rn(__fmul_rn(d1, h), cy);
    float pw  = __fmul_rn(exp_cr(d2), w);
    float ph  = __fmul_rn(exp_cr(d3), h);
    float hx  = __fmul_rn(0.5f, pw);
    float hy  = __fmul_rn(0.5f, ph);
    float x1  = __fsub_rn(pcx, hx);
    float y1  = __fsub_rn(pcy, hy);
    float x2  = __fadd_rn(pcx, hx);
    float y2  = __fadd_rn(pcy, hy);

    float imh = iminfo[b*4+0], imw = iminfo[b*4+1];
    float sh  = iminfo[b*4+2], sw  = iminfo[b*4+3];
    float mw  = imw - 1.0f, mh = imh - 1.0f;
    x1 = fminf(fmaxf(x1, 0.0f), mw);
    y1 = fminf(fmaxf(y1, 0.0f), mh);
    x2 = fminf(fmaxf(x2, 0.0f), mw);
    y2 = fminf(fmaxf(y2, 0.0f), mh);

    float ws = x2 - x1 + 1.0f;
    float hs = y2 - y1 + 1.0f;
    bool valid = (ws >= __fmul_rn(16.0f, sw)) && (hs >= __fmul_rn(16.0f, sh));

    // 32-bit composite key: bits[30,32)=batch, bits[0,30)=descending-score code.
    // p in [0,1] -> bits(p) in [0, 0x3F800000] < 2^30, monotone in p.
    // desc = 0x3F800000 - bits(p): ascending sort == descending score;
    // stability keeps lower index first on ties (top_k semantics).
    // invalid -> 0x3FFFFFFF (> any valid code): sinks to the end of the batch.
    unsigned int desc = valid ? (0x3F800000u - __float_as_uint(p)) : 0x3FFFFFFFu;
    unsigned int key  = ((unsigned int)b << 30) | desc;

    int gi = b*N_ANCH + i;
    g_keys[gi]  = key;
    g_vals[gi]  = gi;
    g_boxes[gi] = make_float4(x1, y1, x2, y2);
}

// ---------------- kernel 2: gather top-PRE boxes per batch + areas ----------------
__global__ void gather_kernel()
{
    int t = blockIdx.x * blockDim.x + threadIdx.x;
    if (t >= B_*PRE) return;
    int b = t / PRE;
    int r = t % PRE;
    int v = g_vals_out[b*N_ANCH + r];
    float4 bx = g_boxes[v];
    g_sboxes[t] = bx;
    g_sarea[t]  = (bx.z - bx.x + 1.0f) * (bx.w - bx.y + 1.0f);
}

// ---------------- kernel 3: IoU suppression bitmask (upper triangle only) ----------------
// DIAG=false: full 64x64 tile, no per-iter row test.
// DIAG=true : diagonal tile; compute all, post-mask bits k<=t.
template <bool DIAG>
__device__ __forceinline__ void mask_tile_body(int cb, int rb, int b)
{
    __shared__ float4 cbox[64];
    __shared__ float  carea[64];
    int t  = threadIdx.x;
    int j0 = cb * 64;
    int jj = j0 + t;
    if (jj < PRE) { cbox[t] = g_sboxes[b*PRE + jj]; carea[t] = g_sarea[b*PRE + jj]; }
    __syncthreads();

    int i = rb * 64 + t;
    if (i >= PRE) return;
    float4 bi = g_sboxes[b*PRE + i];
    float  ai = g_sarea [b*PRE + i];

    unsigned long long bits = 0ull;
    int jmax = min(64, PRE - j0);
    #pragma unroll 8
    for (int k = 0; k < jmax; k++) {
        float4 bj = cbox[k];
        float xx1 = fmaxf(bi.x, bj.x);
        float yy1 = fmaxf(bi.y, bj.y);
        float xx2 = fminf(bi.z, bj.z);
        float yy2 = fminf(bi.w, bj.w);
        float iw = fmaxf(xx2 - xx1 + 1.0f, 0.0f);
        float ih = fmaxf(yy2 - yy1 + 1.0f, 0.0f);
        float inter = __fmul_rn(iw, ih);
        float sum   = __fadd_rn(ai, carea[k]);
        // Exact prefilter: iou > 0.7 requires inter > 0.41*sum in real arith;
        // 4*inter >= sum (exact power-of-2 scale, slack 1.6x) is a safe
        // necessary condition -> kept-bit set is bit-identical, div is rare.
        if (__fmul_rn(inter, 4.0f) >= sum) {
            float uni = __fsub_rn(sum, inter);       // exact ref op order
            float iou = __fdiv_rn(inter, uni);       // IEEE div, matches ref
            if (iou > NMS_THR) bits |= (1ull << k);
        }
    }
    if (DIAG) {
        // keep only strictly-later columns (j > i  <=>  k > t)
        bits = (t == 63) ? 0ull : (bits & (~0ull << (t + 1)));
    }
    g_mask[((size_t)(b*PRE + i))*NW + cb] = bits;
}

__global__ void nms_mask_kernel()
{
    int cb = blockIdx.x;           // column 64-block
    int rb = blockIdx.y;           // row 64-block
    int b  = blockIdx.z;
    if (cb < rb) return;           // lower triangle: words stay zero (zero-init)
    if (cb == rb) mask_tile_body<true >(cb, rb, b);
    else          mask_tile_body<false>(cb, rb, b);
}

// ---------------- kernel 4: warp-serial greedy scan + output write ----------------
__global__ void nms_scan_kernel(float* __restrict__ out)
{
    int b    = blockIdx.x;
    int lane = threadIdx.x;        // 32 threads
    const unsigned FULL = 0xFFFFFFFFu;

    __shared__ unsigned long long removed[NW];
    __shared__ int keptList[POST];
    for (int w = lane; w < NW; w += 32) removed[w] = 0ull;
    __syncwarp();

    int kept = 0;
    for (int c = 0; c < NW && kept < POST; c++) {
        int r0 = c * 64;
        int ra = r0 + lane, rb2 = r0 + 32 + lane;

        // validity from sorted 32-bit keys: invalid <=> low-30 code == 0x3FFFFFFF
        bool va = (ra  < PRE) && ((g_keys_out[b*N_ANCH + ra ] & 0x3FFFFFFFu) != 0x3FFFFFFFu);
        bool vb = (rb2 < PRE) && ((g_keys_out[b*N_ANCH + rb2] & 0x3FFFFFFFu) != 0x3FFFFFFFu);
        unsigned lo = __ballot_sync(FULL, va);
        unsigned hi = __ballot_sync(FULL, vb);
        unsigned long long validm = (unsigned long long)lo | ((unsigned long long)hi << 32);

        // intra-chunk suppression words, register-resident (2 rows per lane)
        unsigned long long m0 = (ra  < PRE) ? g_mask[((size_t)(b*PRE + ra ))*NW + c] : 0ull;
        unsigned long long m1 = (rb2 < PRE) ? g_mask[((size_t)(b*PRE + rb2))*NW + c] : 0ull;

        unsigned long long cand = validm & ~removed[c];
        unsigned long long keptbits = 0ull;
        while (cand && kept < POST) {                 // warp-uniform
            int l = __ffsll((long long)cand) - 1;
            keptList[kept] = r0 + l;                  // same value from all lanes
            kept++;
            keptbits |= (1ull << l);
            unsigned long long intra = (l < 32) ? __shfl_sync(FULL, m0, l)
                                                : __shfl_sync(FULL, m1, l - 32);
            cand &= ~intra;
            cand &= ~(1ull << l);
        }

        // deferred full-row ORs: loads for all newly-kept rows in flight together
        if (keptbits) {
            unsigned long long acc0 = 0, acc1 = 0, acc2 = 0;
            int w0 = lane, w1 = lane + 32, w2 = lane + 64;
            unsigned long long kb2 = keptbits;
            while (kb2) {
                int l = __ffsll((long long)kb2) - 1;
                kb2 &= kb2 - 1;
                const unsigned long long* row = &g_mask[((size_t)(b*PRE + r0 + l))*NW];
                acc0 |= row[w0];
                if (w1 < NW) acc1 |= row[w1];
                if (w2 < NW) acc2 |= row[w2];
            }
            removed[w0] |= acc0;
            if (w1 < NW) removed[w1] |= acc1;
            if (w2 < NW) removed[w2] |= acc2;
        }
        __syncwarp();
    }

    // output: (B, POST, 5) rows [b, x1, y1, x2, y2]; empty rows [b, 0,0,0,0]
    for (int r = lane; r < POST; r += 32) {
        float* o = out + ((size_t)(b*POST + r))*5;
        if (r < kept) {
            float4 bx = g_sboxes[b*PRE + keptList[r]];
            o[0] = (float)b; o[1] = bx.x; o[2] = bx.y; o[3] = bx.z; o[4] = bx.w;
        } else {
            o[0] = (float)b; o[1] = 0.0f; o[2] = 0.0f; o[3] = 0.0f; o[4] = 0.0f;
        }
    }
}

// ---------------- launch ----------------
extern "C" void kernel_launch(void* const* d_in, const int* in_sizes, int n_in,
                              void* d_out, int out_size)
{
    const float* scores  = (const float*)d_in[0];
    const float* deltas  = (const float*)d_in[1];
    const float* anchors = (const float*)d_in[2];
    const float* iminfo  = (const float*)d_in[3];
    float* out = (float*)d_out;

    void *keys, *keysOut, *vals, *valsOut, *temp;
    cudaGetSymbolAddress(&keys,    g_keys);
    cudaGetSymbolAddress(&keysOut, g_keys_out);
    cudaGetSymbolAddress(&vals,    g_vals);
    cudaGetSymbolAddress(&valsOut, g_vals_out);
    cudaGetSymbolAddress(&temp,    g_temp);

    const int total = B_ * N_ANCH;
    prep_kernel<<<(total + 255) / 256, 256>>>(scores, deltas, anchors, iminfo);

    // one stable ascending radix sort over 32-bit composite keys (4 passes)
    size_t temp_bytes = 0;
    cub::DeviceRadixSort::SortPairs(nullptr, temp_bytes,
        (const unsigned int*)keys, (unsigned int*)keysOut,
        (const int*)vals, (int*)valsOut, total, 0, 32);
    if (temp_bytes <= sizeof(g_temp)) {
        cub::DeviceRadixSort::SortPairs(temp, temp_bytes,
            (const unsigned int*)keys, (unsigned int*)keysOut,
            (const int*)vals, (int*)valsOut, total, 0, 32, (cudaStream_t)0);
    }

    gather_kernel<<<(B_*PRE + 255) / 256, 256>>>();

    dim3 mgrid(NW, NW, B_);
    nms_mask_kernel<<<mgrid, 64>>>();

    nms_scan_kernel<<<B_, 32>>>(out);
}